// round 15
// baseline (speedup 1.0000x reference)
#include <cuda_runtime.h>
#include <cuda_fp16.h>
#include <cstdint>

#define BATCH  8
#define S_LEN  1024
#define DMODEL 768
#define NH     12
#define DK     64
#define MTOT   (BATCH*S_LEN)
#define CEXP   0.18033688011112042f   /* log2(e)/8 : folded into Wq, bq */

// ---------------------------------------------------------------------------
// Scratch (device globals — sanctioned no-alloc scratch)
// ---------------------------------------------------------------------------
__device__ __align__(16) __half g_q [BATCH*NH*S_LEN*DK];   // [B,H,S,dk] (pre-scaled by CEXP)
__device__ __align__(16) __half g_k [BATCH*NH*S_LEN*DK];   // [B,H,S,dk]
__device__ __align__(16) __half g_vt[BATCH*NH*DK*S_LEN];   // [B,H,dk,S]
__device__ __align__(16) __half g_c [MTOT*DMODEL];         // [B,S,H*dk]
__device__ __align__(16) __half g_wq[DMODEL*DMODEL];       // fp16 weights (wq scaled by CEXP)
__device__ __align__(16) __half g_wk[DMODEL*DMODEL];
__device__ __align__(16) __half g_wv[DMODEL*DMODEL];
__device__ __align__(16) __half g_wo[DMODEL*DMODEL];

// ---------------------------------------------------------------------------
// Helpers
// ---------------------------------------------------------------------------
__device__ __forceinline__ unsigned pack_h2(float a, float b) {
    __half2 h = __floats2half2_rn(a, b);
    return *reinterpret_cast<unsigned*>(&h);
}
__device__ __forceinline__ unsigned ex2h2(float a, float b) {
    unsigned x = pack_h2(a, b), y;
    asm("ex2.approx.f16x2 %0, %1;" : "=r"(y) : "r"(x));
    return y;
}
__device__ __forceinline__ void mma16(float* c, const unsigned* a, const unsigned* b) {
    asm volatile(
        "mma.sync.aligned.m16n8k16.row.col.f32.f16.f16.f32 "
        "{%0,%1,%2,%3}, {%4,%5,%6,%7}, {%8,%9}, {%0,%1,%2,%3};"
        : "+f"(c[0]), "+f"(c[1]), "+f"(c[2]), "+f"(c[3])
        : "r"(a[0]), "r"(a[1]), "r"(a[2]), "r"(a[3]),
          "r"(b[0]), "r"(b[1]));
}
__device__ __forceinline__ void ldsm_x4(unsigned* r, unsigned addr) {
    asm volatile("ldmatrix.sync.aligned.m8n8.x4.shared.b16 {%0,%1,%2,%3}, [%4];"
                 : "=r"(r[0]), "=r"(r[1]), "=r"(r[2]), "=r"(r[3]) : "r"(addr));
}
__device__ __forceinline__ void cp16(unsigned sa, const void* g) {
    asm volatile("cp.async.cg.shared.global [%0], [%1], 16;" :: "r"(sa), "l"(g));
}
__device__ __forceinline__ void cp_commit() { asm volatile("cp.async.commit_group;"); }
template<int N>
__device__ __forceinline__ void cp_wait() { asm volatile("cp.async.wait_group %0;" :: "n"(N)); }
__device__ __forceinline__ unsigned smem_u32(const void* p) {
    return (unsigned)__cvta_generic_to_shared(p);
}

// ---------------------------------------------------------------------------
// fp32 -> fp16 weight conversion; Wq additionally scaled by CEXP.
// ---------------------------------------------------------------------------
#define NW8  (DMODEL * DMODEL / 8)
#define BW   (NW8 / 256)
#define CVT_BLOCKS (4 * BW)

__global__ __launch_bounds__(256)
void cvt_w(const float* __restrict__ wq, const float* __restrict__ wk,
           const float* __restrict__ wv, const float* __restrict__ wo)
{
    int b = blockIdx.x;
    const float* src;
    __half* dst;
    int base;
    float sc = 1.0f;
    if      (b < BW)     { src = wq; dst = g_wq; base = 0;      sc = CEXP; }
    else if (b < 2 * BW) { src = wk; dst = g_wk; base = BW; }
    else if (b < 3 * BW) { src = wv; dst = g_wv; base = 2 * BW; }
    else                 { src = wo; dst = g_wo; base = 3 * BW; }
    int i = (b - base) * 256 + threadIdx.x;
    float4 a4 = reinterpret_cast<const float4*>(src)[2 * i];
    float4 b4 = reinterpret_cast<const float4*>(src)[2 * i + 1];
    uint4 u;
    u.x = pack_h2(a4.x * sc, a4.y * sc); u.y = pack_h2(a4.z * sc, a4.w * sc);
    u.z = pack_h2(b4.x * sc, b4.y * sc); u.w = pack_h2(b4.z * sc, b4.w * sc);
    reinterpret_cast<uint4*>(dst)[i] = u;
}

// ---------------------------------------------------------------------------
// Projection GEMM core — R15: software-pipelined fragments.
// Per k-slab, kk+1's A/B LDSM fragments are prefetched into a second register
// buffer while kk's MMA burst issues, hiding LDSM latency under tensor work.
// ---------------------------------------------------------------------------
#define PLD   36
#define ABUF  (128 * PLD)

template<int BN, bool AF32>
__device__ __forceinline__ void gemm_core(const __half* __restrict__ Ah,
                                          const float*  __restrict__ Af,
                                          const __half* __restrict__ Bg,
                                          unsigned* psm, int bm, int bn,
                                          float acc[4][BN / 32][4])
{
    constexpr int NJ    = BN / 64;
    constexpr int BBUF  = BN * PLD;
    constexpr int STG_W = ABUF + BBUF;
    constexpr int BCH   = BN / 32;

    const int tid = threadIdx.x, wid = tid >> 5, lane = tid & 31;
    const int wn = (wid & 3) * (BN / 4);
    const int wm = (wid >> 2) * 64;
    const int sr = tid >> 3, sc = tid & 7;

    auto stageB = [&](int t) {
        unsigned* buf = psm + (t % 3) * STG_W;
        if constexpr (!AF32) {
            #pragma unroll
            for (int i = 0; i < 4; i++) {
                int r = sr + i * 32;
                cp16(smem_u32(buf + r * PLD) + sc * 16,
                     Ah + (size_t)(bm + r) * DMODEL + t * 64 + sc * 8);
            }
        }
        #pragma unroll
        for (int i = 0; i < BCH; i++) {
            int r = sr + i * 32;
            cp16(smem_u32(buf + ABUF + r * PLD) + sc * 16,
                 Bg + (size_t)(bn + r) * DMODEL + t * 64 + sc * 8);
        }
        cp_commit();
    };

    const int ar0 = tid >> 4, ac = tid & 15;
    float4 areg[AF32 ? 8 : 1];
    auto ldgA = [&](int t) {
        if constexpr (AF32) {
            #pragma unroll
            for (int i = 0; i < 8; i++) {
                int r = ar0 + i * 16;
                areg[i] = *reinterpret_cast<const float4*>(
                    Af + (size_t)(bm + r) * DMODEL + t * 64 + ac * 4);
            }
        }
    };
    auto stsA = [&](int t) {
        if constexpr (AF32) {
            unsigned* buf = psm + (t % 3) * STG_W;
            #pragma unroll
            for (int i = 0; i < 8; i++) {
                int r = ar0 + i * 16;
                uint2 u;
                u.x = pack_h2(areg[i].x, areg[i].y);
                u.y = pack_h2(areg[i].z, areg[i].w);
                *reinterpret_cast<uint2*>(
                    reinterpret_cast<char*>(buf + r * PLD) + ac * 8) = u;
            }
        }
    };

    #pragma unroll
    for (int i = 0; i < 4; i++)
        #pragma unroll
        for (int j = 0; j < BN / 32; j++)
            #pragma unroll
            for (int q = 0; q < 4; q++) acc[i][j][q] = 0.f;

    const unsigned aoff = ((wm + (lane & 15)) * PLD + ((lane >> 4) << 2)) * 4;
    const unsigned boff = (ABUF + (wn + (lane & 7) + ((lane >> 4) << 3)) * PLD
                           + (((lane >> 3) & 1) << 2)) * 4;

    if constexpr (AF32) {
        ldgA(0); stsA(0);
        ldgA(1); stsA(1);
    }
    stageB(0); stageB(1);

    for (int t = 0; t < 12; t++) {
        if (t < 11) cp_wait<1>();
        else        cp_wait<0>();
        __syncthreads();
        if (t + 2 < 12) { stageB(t + 2); ldgA(t + 2); }

        unsigned base = smem_u32(psm + (t % 3) * STG_W);
        unsigned af[2][4][4], bf[2][NJ][4];
        auto ldfrag = [&](int kk, int p) {
            #pragma unroll
            for (int i = 0; i < 4; i++)
                ldsm_x4(af[p][i], base + aoff + i * (16 * PLD * 4) + kk * 32);
            #pragma unroll
            for (int jp = 0; jp < NJ; jp++)
                ldsm_x4(bf[p][jp], base + boff + jp * (16 * PLD * 4) + kk * 32);
        };
        ldfrag(0, 0);
        #pragma unroll
        for (int kk = 0; kk < 4; kk++) {
            const int cur = kk & 1;
            if (kk < 3) ldfrag(kk + 1, cur ^ 1);   // prefetch under MMA burst
            #pragma unroll
            for (int jp = 0; jp < NJ; jp++)
                #pragma unroll
                for (int i = 0; i < 4; i++) {
                    mma16(acc[i][2 * jp],     af[cur][i], bf[cur][jp]);
                    mma16(acc[i][2 * jp + 1], af[cur][i], bf[cur][jp] + 2);
                }
        }
        if (t + 2 < 12) stsA(t + 2);
    }
}

#define PJ_SMEM_QKV (3 * (ABUF + 256 * PLD) * 4)   // 165888 B
#define PJ_SMEM_O   (3 * (ABUF + 192 * PLD) * 4)   // 138240 B

// ---- fused Q/K/V projection (BN=256, fp32 A): blockIdx.z = problem ---------
__global__ __launch_bounds__(256, 1)
void proj_qkv(const float* __restrict__ xq, const float* __restrict__ xk,
              const float* __restrict__ xv,
              const float* __restrict__ bq, const float* __restrict__ bk,
              const float* __restrict__ bv)
{
    extern __shared__ unsigned psm[];
    const int mode = blockIdx.z;                 // 0=Q 1=K 2=V
    const int bm = blockIdx.y * 128, bn = blockIdx.x * 256;
    const int tid = threadIdx.x, wid = tid >> 5, lane = tid & 31;
    const int rq = lane >> 2, cq = lane & 3;
    const int wm = (wid >> 2) * 64, wn = (wid & 3) * 64;

    const float* Af = (mode == 0) ? xq : (mode == 1) ? xk : xv;
    const __half* Bg = (mode == 0) ? g_wq : (mode == 1) ? g_wk : g_wv;
    const float* bias = (mode == 0) ? bq : (mode == 1) ? bk : bv;
    const float bsc = (mode == 0) ? CEXP : 1.0f;   // bq scaled to match wq

    float acc[4][8][4];
    gemm_core<256, true>(nullptr, Af, Bg, psm, bm, bn, acc);

    #pragma unroll
    for (int i = 0; i < 4; i++) {
        #pragma unroll
        for (int j = 0; j < 8; j++) {
            int r = bm + wm + i * 16 + rq;
            int c = bn + wn + j * 8 + 2 * cq;
            float b0 = bias[c] * bsc, b1 = bias[c + 1] * bsc;
            float v00 = acc[i][j][0] + b0, v01 = acc[i][j][1] + b1;
            float v10 = acc[i][j][2] + b0, v11 = acc[i][j][3] + b1;
            int h = c >> 6, d = c & (DK - 1);
            if (mode == 2) {
                auto put = [&](int row, int dd, float v) {
                    int b = row >> 10, s = row & (S_LEN - 1);
                    g_vt[(((size_t)(b * NH + h)) * DK + dd) * S_LEN + s] = __float2half(v);
                };
                put(r, d, v00);     put(r, d + 1, v01);
                put(r + 8, d, v10); put(r + 8, d + 1, v11);
            } else {
                __half* dst = (mode == 0) ? g_q : g_k;
                auto put2 = [&](int row, float a, float bb) {
                    int b = row >> 10, s = row & (S_LEN - 1);
                    *reinterpret_cast<unsigned*>(
                        dst + (((size_t)(b * NH + h)) * S_LEN + s) * DK + d) = pack_h2(a, bb);
                };
                put2(r, v00, v01);
                put2(r + 8, v10, v11);
            }
        }
    }
}

// ---- output projection (BN=192, fp16 A=g_c) --------------------------------
__global__ __launch_bounds__(256, 1)
void proj_o(const float* __restrict__ bias, float* __restrict__ Og)
{
    extern __shared__ unsigned psm[];
    const int bm = blockIdx.y * 128, bn = blockIdx.x * 192;
    const int tid = threadIdx.x, wid = tid >> 5, lane = tid & 31;
    const int rq = lane >> 2, cq = lane & 3;
    const int wm = (wid >> 2) * 64, wn = (wid & 3) * 48;

    float acc[4][6][4];
    gemm_core<192, false>(g_c, nullptr, g_wo, psm, bm, bn, acc);

    #pragma unroll
    for (int i = 0; i < 4; i++) {
        #pragma unroll
        for (int j = 0; j < 6; j++) {
            int r = bm + wm + i * 16 + rq;
            int c = bn + wn + j * 8 + 2 * cq;
            float b0 = bias[c], b1 = bias[c + 1];
            float2 v0; v0.x = acc[i][j][0] + b0; v0.y = acc[i][j][1] + b1;
            float2 v1; v1.x = acc[i][j][2] + b0; v1.y = acc[i][j][3] + b1;
            *reinterpret_cast<float2*>(Og + (size_t)r * DMODEL + c)       = v0;
            *reinterpret_cast<float2*>(Og + (size_t)(r + 8) * DMODEL + c) = v1;
        }
    }
}

// ---------------------------------------------------------------------------
// FP16 flash attention — R14 shape (8 warps x 16 q-rows, fixed-shift softmax,
// cexp pre-folded into Q; p = exp2(s) straight from the MMA accumulator).
// ---------------------------------------------------------------------------
#define FL_S 36
#define FL_KV (64 * FL_S)
#define FA_SMEM ((128 * FL_S + 6 * FL_KV) * 4)   // 73728 B

__global__ __launch_bounds__(256, 2)
void flash_attn()
{
    extern __shared__ __align__(16) unsigned smx[];
    unsigned* sQ = smx;
    unsigned* sK = sQ + 128 * FL_S;
    unsigned* sV = sK + 3 * FL_KV;

    const int z    = blockIdx.y;
    const int qt   = blockIdx.x;
    const int tid  = threadIdx.x;
    const int warp = tid >> 5;
    const int lane = tid & 31;
    const int rq   = lane >> 2;
    const int cq   = lane & 3;

    const __half* Qg = g_q  + (size_t)z * S_LEN * DK + (size_t)qt * 128 * DK;
    const __half* Kg = g_k  + (size_t)z * S_LEN * DK;
    const __half* Vg = g_vt + (size_t)z * DK * S_LEN;

    const int sr = tid >> 2, sc = tid & 3;
    auto stage = [&](int kt) {
        int buf = kt % 3;
        unsigned kdst = smem_u32(&sK[buf * FL_KV + sr * FL_S]);
        const __half* ksrc = Kg + (size_t)(kt * 64 + sr) * DK;
        cp16(kdst + sc * 16,       ksrc + sc * 8);
        cp16(kdst + (sc + 4) * 16, ksrc + (sc + 4) * 8);
        unsigned vdst = smem_u32(&sV[buf * FL_KV + sr * FL_S]);
        const __half* vsrc = Vg + (size_t)sr * S_LEN + kt * 64;
        cp16(vdst + sc * 16,       vsrc + sc * 8);
        cp16(vdst + (sc + 4) * 16, vsrc + (sc + 4) * 8);
        cp_commit();
    };

    stage(0);
    stage(1);

    #pragma unroll
    for (int i = 0; i < 8; i++) {
        int idx = tid + i * 256;
        int r = idx >> 4, c = idx & 15;
        uint2 v = *reinterpret_cast<const uint2*>(Qg + r * DK + c * 4);
        *reinterpret_cast<uint2*>(&sQ[r * FL_S + c * 2]) = v;
    }

    float o[8][4];
    #pragma unroll
    for (int j = 0; j < 8; j++)
        #pragma unroll
        for (int q = 0; q < 4; q++) o[j][q] = 0.f;
    float lacc[4] = {0.f, 0.f, 0.f, 0.f};
    const unsigned ones2[2] = {0x3C003C00u, 0x3C003C00u};

    const int ra = warp * 16 + rq;

    const unsigned qaddr = smem_u32(sQ) +
        ((warp * 16 + (lane & 15)) * FL_S + ((lane >> 4) << 2)) * 4;
    const unsigned kvoff =
        (((lane & 7) + ((lane >> 4) << 3)) * FL_S + (((lane >> 3) & 1) << 2)) * 4;

    for (int kt = 0; kt < S_LEN / 64; kt++) {
        if (kt < S_LEN / 64 - 1) cp_wait<1>();
        else                     cp_wait<0>();
        __syncthreads();
        if (kt + 2 < S_LEN / 64) stage(kt + 2);

        const unsigned kaddr = smem_u32(sK + (kt % 3) * FL_KV) + kvoff;
        const unsigned vaddr = smem_u32(sV + (kt % 3) * FL_KV) + kvoff;

        float s[8][4];
        #pragma unroll
        for (int j = 0; j < 8; j++)
            #pragma unroll
            for (int q = 0; q < 4; q++) s[j][q] = 0.f;

        #pragma unroll
        for (int kk = 0; kk < 4; kk++) {
            unsigned a[4];
            ldsm_x4(a, qaddr + kk * 32);
            #pragma unroll
            for (int jp = 0; jp < 4; jp++) {
                unsigned b4[4];
                ldsm_x4(b4, kaddr + jp * (16 * FL_S * 4) + kk * 32);
                mma16(s[2 * jp],     a, b4);
                mma16(s[2 * jp + 1], a, b4 + 2);
            }
        }

        unsigned pf[8][2];
        #pragma unroll
        for (int j = 0; j < 8; j++) {
            pf[j][0] = ex2h2(s[j][0], s[j][1]);
            pf[j][1] = ex2h2(s[j][2], s[j][3]);
        }

        #pragma unroll
        for (int kk = 0; kk < 4; kk++) {
            unsigned a[4] = { pf[2*kk][0], pf[2*kk][1], pf[2*kk+1][0], pf[2*kk+1][1] };
            #pragma unroll
            for (int jp = 0; jp < 4; jp++) {
                unsigned b4[4];
                ldsm_x4(b4, vaddr + jp * (16 * FL_S * 4) + kk * 32);
                mma16(o[2 * jp],     a, b4);
                mma16(o[2 * jp + 1], a, b4 + 2);
            }
            mma16(lacc, a, ones2);
        }
    }

    {
        float inv0 = 1.f / lacc[0], inv1 = 1.f / lacc[2];
        int b = z / NH, h = z % NH;
        int row = qt * 128 + ra;
        __half* base0 = g_c + ((size_t)b * S_LEN + row) * DMODEL + h * DK;
        __half* base1 = base0 + 8 * DMODEL;
        #pragma unroll
        for (int j = 0; j < 8; j++) {
            int cc = j * 8 + 2 * cq;
            *reinterpret_cast<unsigned*>(base0 + cc) = pack_h2(o[j][0] * inv0, o[j][1] * inv0);
            *reinterpret_cast<unsigned*>(base1 + cc) = pack_h2(o[j][2] * inv1, o[j][3] * inv1);
        }
    }
}

// ---------------------------------------------------------------------------
// Launch
// ---------------------------------------------------------------------------
extern "C" void kernel_launch(void* const* d_in, const int* in_sizes, int n_in,
                              void* d_out, int out_size)
{
    const float* key   = (const float*)d_in[0];
    const float* query = (const float*)d_in[1];
    const float* value = (const float*)d_in[2];
    const float* Wk    = (const float*)d_in[3];
    const float* bk    = (const float*)d_in[4];
    const float* Wq    = (const float*)d_in[5];
    const float* bq    = (const float*)d_in[6];
    const float* Wv    = (const float*)d_in[7];
    const float* bv    = (const float*)d_in[8];
    const float* Wo    = (const float*)d_in[9];
    const float* bo    = (const float*)d_in[10];
    float* out = (float*)d_out;

    cvt_w<<<CVT_BLOCKS, 256>>>(Wq, Wk, Wv, Wo);

    cudaFuncSetAttribute(proj_qkv, cudaFuncAttributeMaxDynamicSharedMemorySize, PJ_SMEM_QKV);
    cudaFuncSetAttribute(proj_o,   cudaFuncAttributeMaxDynamicSharedMemorySize, PJ_SMEM_O);

    proj_qkv<<<dim3(DMODEL / 256, MTOT / 128, 3), 256, PJ_SMEM_QKV>>>(
        query, key, value, bq, bk, bv);

    cudaFuncSetAttribute(flash_attn, cudaFuncAttributeMaxDynamicSharedMemorySize, FA_SMEM);
    flash_attn<<<dim3(S_LEN / 128, BATCH * NH), 256, FA_SMEM>>>();

    proj_o<<<dim3(DMODEL / 192, MTOT / 128), 256, PJ_SMEM_O>>>(bo, out);
}

// round 16
// speedup vs baseline: 1.0062x; 1.0062x over previous
#include <cuda_runtime.h>
#include <cuda_fp16.h>
#include <cstdint>

#define BATCH  8
#define S_LEN  1024
#define DMODEL 768
#define NH     12
#define DK     64
#define MTOT   (BATCH*S_LEN)
#define CEXP   0.18033688011112042f   /* log2(e)/8 : folded into Wq, bq */

// ---------------------------------------------------------------------------
// Scratch (device globals — sanctioned no-alloc scratch)
// ---------------------------------------------------------------------------
__device__ __align__(16) __half g_q [BATCH*NH*S_LEN*DK];   // [B,H,S,dk] (pre-scaled by CEXP)
__device__ __align__(16) __half g_k [BATCH*NH*S_LEN*DK];   // [B,H,S,dk]
__device__ __align__(16) __half g_vt[BATCH*NH*DK*S_LEN];   // [B,H,dk,S]
__device__ __align__(16) __half g_c [MTOT*DMODEL];         // [B,S,H*dk]
__device__ __align__(16) __half g_wq[DMODEL*DMODEL];       // fp16 weights (wq scaled by CEXP)
__device__ __align__(16) __half g_wk[DMODEL*DMODEL];
__device__ __align__(16) __half g_wv[DMODEL*DMODEL];
__device__ __align__(16) __half g_wo[DMODEL*DMODEL];

// ---------------------------------------------------------------------------
// Helpers
// ---------------------------------------------------------------------------
__device__ __forceinline__ unsigned pack_h2(float a, float b) {
    __half2 h = __floats2half2_rn(a, b);
    return *reinterpret_cast<unsigned*>(&h);
}
__device__ __forceinline__ unsigned ex2h2(float a, float b) {
    unsigned x = pack_h2(a, b), y;
    asm("ex2.approx.f16x2 %0, %1;" : "=r"(y) : "r"(x));
    return y;
}
__device__ __forceinline__ void mma16(float* c, const unsigned* a, const unsigned* b) {
    asm volatile(
        "mma.sync.aligned.m16n8k16.row.col.f32.f16.f16.f32 "
        "{%0,%1,%2,%3}, {%4,%5,%6,%7}, {%8,%9}, {%0,%1,%2,%3};"
        : "+f"(c[0]), "+f"(c[1]), "+f"(c[2]), "+f"(c[3])
        : "r"(a[0]), "r"(a[1]), "r"(a[2]), "r"(a[3]),
          "r"(b[0]), "r"(b[1]));
}
__device__ __forceinline__ void ldsm_x4(unsigned* r, unsigned addr) {
    asm volatile("ldmatrix.sync.aligned.m8n8.x4.shared.b16 {%0,%1,%2,%3}, [%4];"
                 : "=r"(r[0]), "=r"(r[1]), "=r"(r[2]), "=r"(r[3]) : "r"(addr));
}
__device__ __forceinline__ void cp16(unsigned sa, const void* g) {
    asm volatile("cp.async.cg.shared.global [%0], [%1], 16;" :: "r"(sa), "l"(g));
}
__device__ __forceinline__ void cp_commit() { asm volatile("cp.async.commit_group;"); }
template<int N>
__device__ __forceinline__ void cp_wait() { asm volatile("cp.async.wait_group %0;" :: "n"(N)); }
__device__ __forceinline__ unsigned smem_u32(const void* p) {
    return (unsigned)__cvta_generic_to_shared(p);
}

// ---------------------------------------------------------------------------
// fp32 -> fp16 weight conversion; Wq additionally scaled by CEXP.
// ---------------------------------------------------------------------------
#define NW8  (DMODEL * DMODEL / 8)
#define BW   (NW8 / 256)
#define CVT_BLOCKS (4 * BW)

__global__ __launch_bounds__(256)
void cvt_w(const float* __restrict__ wq, const float* __restrict__ wk,
           const float* __restrict__ wv, const float* __restrict__ wo)
{
    int b = blockIdx.x;
    const float* src;
    __half* dst;
    int base;
    float sc = 1.0f;
    if      (b < BW)     { src = wq; dst = g_wq; base = 0;      sc = CEXP; }
    else if (b < 2 * BW) { src = wk; dst = g_wk; base = BW; }
    else if (b < 3 * BW) { src = wv; dst = g_wv; base = 2 * BW; }
    else                 { src = wo; dst = g_wo; base = 3 * BW; }
    int i = (b - base) * 256 + threadIdx.x;
    float4 a4 = reinterpret_cast<const float4*>(src)[2 * i];
    float4 b4 = reinterpret_cast<const float4*>(src)[2 * i + 1];
    uint4 u;
    u.x = pack_h2(a4.x * sc, a4.y * sc); u.y = pack_h2(a4.z * sc, a4.w * sc);
    u.z = pack_h2(b4.x * sc, b4.y * sc); u.w = pack_h2(b4.z * sc, b4.w * sc);
    reinterpret_cast<uint4*>(dst)[i] = u;
}

// ---------------------------------------------------------------------------
// Projection GEMM core (R14 inner loop — ptxas schedules fragments fine)
// ---------------------------------------------------------------------------
#define PLD   36
#define ABUF  (128 * PLD)

template<int BN, bool AF32>
__device__ __forceinline__ void gemm_core(const __half* __restrict__ Ah,
                                          const float*  __restrict__ Af,
                                          const __half* __restrict__ Bg,
                                          unsigned* psm, int bm, int bn,
                                          float acc[4][BN / 32][4])
{
    constexpr int NJ    = BN / 64;
    constexpr int BBUF  = BN * PLD;
    constexpr int STG_W = ABUF + BBUF;
    constexpr int BCH   = BN / 32;

    const int tid = threadIdx.x, wid = tid >> 5, lane = tid & 31;
    const int wn = (wid & 3) * (BN / 4);
    const int wm = (wid >> 2) * 64;
    const int sr = tid >> 3, sc = tid & 7;

    auto stageB = [&](int t) {
        unsigned* buf = psm + (t % 3) * STG_W;
        if constexpr (!AF32) {
            #pragma unroll
            for (int i = 0; i < 4; i++) {
                int r = sr + i * 32;
                cp16(smem_u32(buf + r * PLD) + sc * 16,
                     Ah + (size_t)(bm + r) * DMODEL + t * 64 + sc * 8);
            }
        }
        #pragma unroll
        for (int i = 0; i < BCH; i++) {
            int r = sr + i * 32;
            cp16(smem_u32(buf + ABUF + r * PLD) + sc * 16,
                 Bg + (size_t)(bn + r) * DMODEL + t * 64 + sc * 8);
        }
        cp_commit();
    };

    const int ar0 = tid >> 4, ac = tid & 15;
    float4 areg[AF32 ? 8 : 1];
    auto ldgA = [&](int t) {
        if constexpr (AF32) {
            #pragma unroll
            for (int i = 0; i < 8; i++) {
                int r = ar0 + i * 16;
                areg[i] = *reinterpret_cast<const float4*>(
                    Af + (size_t)(bm + r) * DMODEL + t * 64 + ac * 4);
            }
        }
    };
    auto stsA = [&](int t) {
        if constexpr (AF32) {
            unsigned* buf = psm + (t % 3) * STG_W;
            #pragma unroll
            for (int i = 0; i < 8; i++) {
                int r = ar0 + i * 16;
                uint2 u;
                u.x = pack_h2(areg[i].x, areg[i].y);
                u.y = pack_h2(areg[i].z, areg[i].w);
                *reinterpret_cast<uint2*>(
                    reinterpret_cast<char*>(buf + r * PLD) + ac * 8) = u;
            }
        }
    };

    #pragma unroll
    for (int i = 0; i < 4; i++)
        #pragma unroll
        for (int j = 0; j < BN / 32; j++)
            #pragma unroll
            for (int q = 0; q < 4; q++) acc[i][j][q] = 0.f;

    const unsigned aoff = ((wm + (lane & 15)) * PLD + ((lane >> 4) << 2)) * 4;
    const unsigned boff = (ABUF + (wn + (lane & 7) + ((lane >> 4) << 3)) * PLD
                           + (((lane >> 3) & 1) << 2)) * 4;

    if constexpr (AF32) {
        ldgA(0); stsA(0);
        ldgA(1); stsA(1);
    }
    stageB(0); stageB(1);

    for (int t = 0; t < 12; t++) {
        if (t < 11) cp_wait<1>();
        else        cp_wait<0>();
        __syncthreads();
        if (t + 2 < 12) { stageB(t + 2); ldgA(t + 2); }

        unsigned base = smem_u32(psm + (t % 3) * STG_W);
        #pragma unroll
        for (int kk = 0; kk < 4; kk++) {
            unsigned af[4][4], bf[NJ][4];
            #pragma unroll
            for (int i = 0; i < 4; i++)
                ldsm_x4(af[i], base + aoff + i * (16 * PLD * 4) + kk * 32);
            #pragma unroll
            for (int jp = 0; jp < NJ; jp++)
                ldsm_x4(bf[jp], base + boff + jp * (16 * PLD * 4) + kk * 32);
            #pragma unroll
            for (int jp = 0; jp < NJ; jp++)
                #pragma unroll
                for (int i = 0; i < 4; i++) {
                    mma16(acc[i][2 * jp],     af[i], bf[jp]);
                    mma16(acc[i][2 * jp + 1], af[i], bf[jp] + 2);
                }
        }
        if (t + 2 < 12) stsA(t + 2);
    }
}

#define PJ_SMEM_QKV (3 * (ABUF + 256 * PLD) * 4)   // 165888 B
#define PJ_SMEM_O   (3 * (ABUF + 192 * PLD) * 4)   // 138240 B

// ---- fused Q/K/V projection (BN=256, fp32 A): blockIdx.z = problem ---------
__global__ __launch_bounds__(256, 1)
void proj_qkv(const float* __restrict__ xq, const float* __restrict__ xk,
              const float* __restrict__ xv,
              const float* __restrict__ bq, const float* __restrict__ bk,
              const float* __restrict__ bv)
{
    extern __shared__ unsigned psm[];
    const int mode = blockIdx.z;                 // 0=Q 1=K 2=V
    const int bm = blockIdx.y * 128, bn = blockIdx.x * 256;
    const int tid = threadIdx.x, wid = tid >> 5, lane = tid & 31;
    const int rq = lane >> 2, cq = lane & 3;
    const int wm = (wid >> 2) * 64, wn = (wid & 3) * 64;

    const float* Af = (mode == 0) ? xq : (mode == 1) ? xk : xv;
    const __half* Bg = (mode == 0) ? g_wq : (mode == 1) ? g_wk : g_wv;
    const float* bias = (mode == 0) ? bq : (mode == 1) ? bk : bv;
    const float bsc = (mode == 0) ? CEXP : 1.0f;   // bq scaled to match wq

    // PDL: weights come from cvt_w — wait for it before first global read.
    cudaGridDependencySynchronize();

    float acc[4][8][4];
    gemm_core<256, true>(nullptr, Af, Bg, psm, bm, bn, acc);

    #pragma unroll
    for (int i = 0; i < 4; i++) {
        #pragma unroll
        for (int j = 0; j < 8; j++) {
            int r = bm + wm + i * 16 + rq;
            int c = bn + wn + j * 8 + 2 * cq;
            float b0 = bias[c] * bsc, b1 = bias[c + 1] * bsc;
            float v00 = acc[i][j][0] + b0, v01 = acc[i][j][1] + b1;
            float v10 = acc[i][j][2] + b0, v11 = acc[i][j][3] + b1;
            int h = c >> 6, d = c & (DK - 1);
            if (mode == 2) {
                auto put = [&](int row, int dd, float v) {
                    int b = row >> 10, s = row & (S_LEN - 1);
                    g_vt[(((size_t)(b * NH + h)) * DK + dd) * S_LEN + s] = __float2half(v);
                };
                put(r, d, v00);     put(r, d + 1, v01);
                put(r + 8, d, v10); put(r + 8, d + 1, v11);
            } else {
                __half* dst = (mode == 0) ? g_q : g_k;
                auto put2 = [&](int row, float a, float bb) {
                    int b = row >> 10, s = row & (S_LEN - 1);
                    *reinterpret_cast<unsigned*>(
                        dst + (((size_t)(b * NH + h)) * S_LEN + s) * DK + d) = pack_h2(a, bb);
                };
                put2(r, v00, v01);
                put2(r + 8, v10, v11);
            }
        }
    }
}

// ---- output projection (BN=192, fp16 A=g_c) --------------------------------
__global__ __launch_bounds__(256, 1)
void proj_o(const float* __restrict__ bias, float* __restrict__ Og)
{
    extern __shared__ unsigned psm[];
    const int bm = blockIdx.y * 128, bn = blockIdx.x * 192;
    const int tid = threadIdx.x, wid = tid >> 5, lane = tid & 31;
    const int rq = lane >> 2, cq = lane & 3;
    const int wm = (wid >> 2) * 64, wn = (wid & 3) * 48;

    // PDL: g_c comes from flash_attn — wait before first global read.
    cudaGridDependencySynchronize();

    float acc[4][6][4];
    gemm_core<192, false>(g_c, nullptr, g_wo, psm, bm, bn, acc);

    #pragma unroll
    for (int i = 0; i < 4; i++) {
        #pragma unroll
        for (int j = 0; j < 6; j++) {
            int r = bm + wm + i * 16 + rq;
            int c = bn + wn + j * 8 + 2 * cq;
            float b0 = bias[c], b1 = bias[c + 1];
            float2 v0; v0.x = acc[i][j][0] + b0; v0.y = acc[i][j][1] + b1;
            float2 v1; v1.x = acc[i][j][2] + b0; v1.y = acc[i][j][3] + b1;
            *reinterpret_cast<float2*>(Og + (size_t)r * DMODEL + c)       = v0;
            *reinterpret_cast<float2*>(Og + (size_t)(r + 8) * DMODEL + c) = v1;
        }
    }
}

// ---------------------------------------------------------------------------
// FP16 flash attention — R14 shape (8 warps x 16 q-rows, fixed-shift softmax,
// cexp pre-folded into Q; p = exp2(s) straight from the MMA accumulator).
// ---------------------------------------------------------------------------
#define FL_S 36
#define FL_KV (64 * FL_S)
#define FA_SMEM ((128 * FL_S + 6 * FL_KV) * 4)   // 73728 B

__global__ __launch_bounds__(256, 2)
void flash_attn()
{
    extern __shared__ __align__(16) unsigned smx[];
    unsigned* sQ = smx;
    unsigned* sK = sQ + 128 * FL_S;
    unsigned* sV = sK + 3 * FL_KV;

    const int z    = blockIdx.y;
    const int qt   = blockIdx.x;
    const int tid  = threadIdx.x;
    const int warp = tid >> 5;
    const int lane = tid & 31;
    const int rq   = lane >> 2;
    const int cq   = lane & 3;

    const __half* Qg = g_q  + (size_t)z * S_LEN * DK + (size_t)qt * 128 * DK;
    const __half* Kg = g_k  + (size_t)z * S_LEN * DK;
    const __half* Vg = g_vt + (size_t)z * DK * S_LEN;

    const int sr = tid >> 2, sc = tid & 3;
    auto stage = [&](int kt) {
        int buf = kt % 3;
        unsigned kdst = smem_u32(&sK[buf * FL_KV + sr * FL_S]);
        const __half* ksrc = Kg + (size_t)(kt * 64 + sr) * DK;
        cp16(kdst + sc * 16,       ksrc + sc * 8);
        cp16(kdst + (sc + 4) * 16, ksrc + (sc + 4) * 8);
        unsigned vdst = smem_u32(&sV[buf * FL_KV + sr * FL_S]);
        const __half* vsrc = Vg + (size_t)sr * S_LEN + kt * 64;
        cp16(vdst + sc * 16,       vsrc + sc * 8);
        cp16(vdst + (sc + 4) * 16, vsrc + (sc + 4) * 8);
        cp_commit();
    };

    // PDL: q/k/vt come from proj_qkv — wait before first global read.
    cudaGridDependencySynchronize();

    stage(0);
    stage(1);

    #pragma unroll
    for (int i = 0; i < 8; i++) {
        int idx = tid + i * 256;
        int r = idx >> 4, c = idx & 15;
        uint2 v = *reinterpret_cast<const uint2*>(Qg + r * DK + c * 4);
        *reinterpret_cast<uint2*>(&sQ[r * FL_S + c * 2]) = v;
    }

    float o[8][4];
    #pragma unroll
    for (int j = 0; j < 8; j++)
        #pragma unroll
        for (int q = 0; q < 4; q++) o[j][q] = 0.f;
    float lacc[4] = {0.f, 0.f, 0.f, 0.f};
    const unsigned ones2[2] = {0x3C003C00u, 0x3C003C00u};

    const int ra = warp * 16 + rq;

    const unsigned qaddr = smem_u32(sQ) +
        ((warp * 16 + (lane & 15)) * FL_S + ((lane >> 4) << 2)) * 4;
    const unsigned kvoff =
        (((lane & 7) + ((lane >> 4) << 3)) * FL_S + (((lane >> 3) & 1) << 2)) * 4;

    for (int kt = 0; kt < S_LEN / 64; kt++) {
        if (kt < S_LEN / 64 - 1) cp_wait<1>();
        else                     cp_wait<0>();
        __syncthreads();
        if (kt + 2 < S_LEN / 64) stage(kt + 2);

        const unsigned kaddr = smem_u32(sK + (kt % 3) * FL_KV) + kvoff;
        const unsigned vaddr = smem_u32(sV + (kt % 3) * FL_KV) + kvoff;

        float s[8][4];
        #pragma unroll
        for (int j = 0; j < 8; j++)
            #pragma unroll
            for (int q = 0; q < 4; q++) s[j][q] = 0.f;

        #pragma unroll
        for (int kk = 0; kk < 4; kk++) {
            unsigned a[4];
            ldsm_x4(a, qaddr + kk * 32);
            #pragma unroll
            for (int jp = 0; jp < 4; jp++) {
                unsigned b4[4];
                ldsm_x4(b4, kaddr + jp * (16 * FL_S * 4) + kk * 32);
                mma16(s[2 * jp],     a, b4);
                mma16(s[2 * jp + 1], a, b4 + 2);
            }
        }

        unsigned pf[8][2];
        #pragma unroll
        for (int j = 0; j < 8; j++) {
            pf[j][0] = ex2h2(s[j][0], s[j][1]);
            pf[j][1] = ex2h2(s[j][2], s[j][3]);
        }

        #pragma unroll
        for (int kk = 0; kk < 4; kk++) {
            unsigned a[4] = { pf[2*kk][0], pf[2*kk][1], pf[2*kk+1][0], pf[2*kk+1][1] };
            #pragma unroll
            for (int jp = 0; jp < 4; jp++) {
                unsigned b4[4];
                ldsm_x4(b4, vaddr + jp * (16 * FL_S * 4) + kk * 32);
                mma16(o[2 * jp],     a, b4);
                mma16(o[2 * jp + 1], a, b4 + 2);
            }
            mma16(lacc, a, ones2);
        }
    }

    {
        float inv0 = 1.f / lacc[0], inv1 = 1.f / lacc[2];
        int b = z / NH, h = z % NH;
        int row = qt * 128 + ra;
        __half* base0 = g_c + ((size_t)b * S_LEN + row) * DMODEL + h * DK;
        __half* base1 = base0 + 8 * DMODEL;
        #pragma unroll
        for (int j = 0; j < 8; j++) {
            int cc = j * 8 + 2 * cq;
            *reinterpret_cast<unsigned*>(base0 + cc) = pack_h2(o[j][0] * inv0, o[j][1] * inv0);
            *reinterpret_cast<unsigned*>(base1 + cc) = pack_h2(o[j][2] * inv1, o[j][3] * inv1);
        }
    }
}

// ---------------------------------------------------------------------------
// Launch — PDL-chained: each dependent kernel launches with programmatic
// stream serialization so its prologue overlaps the predecessor's drain.
// ---------------------------------------------------------------------------
template<typename... Args>
static inline void launch_pdl(void (*kern)(Args...), dim3 grid, dim3 block,
                              size_t smem, Args... args)
{
    cudaLaunchAttribute attr[1];
    attr[0].id = cudaLaunchAttributeProgrammaticStreamSerialization;
    attr[0].val.programmaticStreamSerializationAllowed = 1;
    cudaLaunchConfig_t cfg = {};
    cfg.gridDim = grid;
    cfg.blockDim = block;
    cfg.dynamicSmemBytes = smem;
    cfg.stream = 0;
    cfg.attrs = attr;
    cfg.numAttrs = 1;
    cudaLaunchKernelEx(&cfg, kern, args...);
}

extern "C" void kernel_launch(void* const* d_in, const int* in_sizes, int n_in,
                              void* d_out, int out_size)
{
    const float* key   = (const float*)d_in[0];
    const float* query = (const float*)d_in[1];
    const float* value = (const float*)d_in[2];
    const float* Wk    = (const float*)d_in[3];
    const float* bk    = (const float*)d_in[4];
    const float* Wq    = (const float*)d_in[5];
    const float* bq    = (const float*)d_in[6];
    const float* Wv    = (const float*)d_in[7];
    const float* bv    = (const float*)d_in[8];
    const float* Wo    = (const float*)d_in[9];
    const float* bo    = (const float*)d_in[10];
    float* out = (float*)d_out;

    cudaFuncSetAttribute(proj_qkv, cudaFuncAttributeMaxDynamicSharedMemorySize, PJ_SMEM_QKV);
    cudaFuncSetAttribute(proj_o,   cudaFuncAttributeMaxDynamicSharedMemorySize, PJ_SMEM_O);
    cudaFuncSetAttribute(flash_attn, cudaFuncAttributeMaxDynamicSharedMemorySize, FA_SMEM);

    cvt_w<<<CVT_BLOCKS, 256>>>(Wq, Wk, Wv, Wo);

    launch_pdl(proj_qkv, dim3(DMODEL / 256, MTOT / 128, 3), dim3(256),
               (size_t)PJ_SMEM_QKV, query, key, value, bq, bk, bv);

    launch_pdl(flash_attn, dim3(S_LEN / 128, BATCH * NH), dim3(256),
               (size_t)FA_SMEM);

    launch_pdl(proj_o, dim3(DMODEL / 192, MTOT / 128), dim3(256),
               (size_t)PJ_SMEM_O, bo, out);
}

// round 17
// speedup vs baseline: 1.0587x; 1.0521x over previous
#include <cuda_runtime.h>
#include <cuda_fp16.h>
#include <cstdint>

#define BATCH  8
#define S_LEN  1024
#define DMODEL 768
#define NH     12
#define DK     64
#define MTOT   (BATCH*S_LEN)
#define CEXP   0.18033688011112042f   /* log2(e)/8 : folded into Wq, bq */

// ---------------------------------------------------------------------------
// Scratch (device globals — sanctioned no-alloc scratch)
// ---------------------------------------------------------------------------
__device__ __align__(16) __half g_q [BATCH*NH*S_LEN*DK];   // [B,H,S,dk] (pre-scaled by CEXP)
__device__ __align__(16) __half g_k [BATCH*NH*S_LEN*DK];   // [B,H,S,dk]
__device__ __align__(16) __half g_vt[BATCH*NH*DK*S_LEN];   // [B,H,dk,S]
__device__ __align__(16) __half g_c [MTOT*DMODEL];         // [B,S,H*dk]
__device__ __align__(16) __half g_wq[DMODEL*DMODEL];       // fp16 weights (wq scaled by CEXP)
__device__ __align__(16) __half g_wk[DMODEL*DMODEL];
__device__ __align__(16) __half g_wv[DMODEL*DMODEL];
__device__ __align__(16) __half g_wo[DMODEL*DMODEL];
__device__ unsigned g_cnt[BATCH * 8];                      // flash->proj_o row-block counters

// ---------------------------------------------------------------------------
// Helpers
// ---------------------------------------------------------------------------
__device__ __forceinline__ unsigned pack_h2(float a, float b) {
    __half2 h = __floats2half2_rn(a, b);
    return *reinterpret_cast<unsigned*>(&h);
}
__device__ __forceinline__ unsigned ex2h2(float a, float b) {
    unsigned x = pack_h2(a, b), y;
    asm("ex2.approx.f16x2 %0, %1;" : "=r"(y) : "r"(x));
    return y;
}
__device__ __forceinline__ void mma16(float* c, const unsigned* a, const unsigned* b) {
    asm volatile(
        "mma.sync.aligned.m16n8k16.row.col.f32.f16.f16.f32 "
        "{%0,%1,%2,%3}, {%4,%5,%6,%7}, {%8,%9}, {%0,%1,%2,%3};"
        : "+f"(c[0]), "+f"(c[1]), "+f"(c[2]), "+f"(c[3])
        : "r"(a[0]), "r"(a[1]), "r"(a[2]), "r"(a[3]),
          "r"(b[0]), "r"(b[1]));
}
__device__ __forceinline__ void ldsm_x4(unsigned* r, unsigned addr) {
    asm volatile("ldmatrix.sync.aligned.m8n8.x4.shared.b16 {%0,%1,%2,%3}, [%4];"
                 : "=r"(r[0]), "=r"(r[1]), "=r"(r[2]), "=r"(r[3]) : "r"(addr));
}
__device__ __forceinline__ void cp16(unsigned sa, const void* g) {
    asm volatile("cp.async.cg.shared.global [%0], [%1], 16;" :: "r"(sa), "l"(g));
}
__device__ __forceinline__ void cp_commit() { asm volatile("cp.async.commit_group;"); }
template<int N>
__device__ __forceinline__ void cp_wait() { asm volatile("cp.async.wait_group %0;" :: "n"(N)); }
__device__ __forceinline__ unsigned smem_u32(const void* p) {
    return (unsigned)__cvta_generic_to_shared(p);
}

// ---------------------------------------------------------------------------
// fp32 -> fp16 weight conversion; Wq additionally scaled by CEXP.
// Also zeroes the cross-kernel dependency counters.
// ---------------------------------------------------------------------------
#define NW8  (DMODEL * DMODEL / 8)
#define BW   (NW8 / 256)
#define CVT_BLOCKS (4 * BW)

__global__ __launch_bounds__(256)
void cvt_w(const float* __restrict__ wq, const float* __restrict__ wk,
           const float* __restrict__ wv, const float* __restrict__ wo)
{
    if (blockIdx.x == 0 && threadIdx.x < BATCH * 8) g_cnt[threadIdx.x] = 0u;

    int b = blockIdx.x;
    const float* src;
    __half* dst;
    int base;
    float sc = 1.0f;
    if      (b < BW)     { src = wq; dst = g_wq; base = 0;      sc = CEXP; }
    else if (b < 2 * BW) { src = wk; dst = g_wk; base = BW; }
    else if (b < 3 * BW) { src = wv; dst = g_wv; base = 2 * BW; }
    else                 { src = wo; dst = g_wo; base = 3 * BW; }
    int i = (b - base) * 256 + threadIdx.x;
    float4 a4 = reinterpret_cast<const float4*>(src)[2 * i];
    float4 b4 = reinterpret_cast<const float4*>(src)[2 * i + 1];
    uint4 u;
    u.x = pack_h2(a4.x * sc, a4.y * sc); u.y = pack_h2(a4.z * sc, a4.w * sc);
    u.z = pack_h2(b4.x * sc, b4.y * sc); u.w = pack_h2(b4.z * sc, b4.w * sc);
    reinterpret_cast<uint4*>(dst)[i] = u;
}

// ---------------------------------------------------------------------------
// Projection GEMM core (R14 inner loop)
// ---------------------------------------------------------------------------
#define PLD   36
#define ABUF  (128 * PLD)

template<int BN, bool AF32>
__device__ __forceinline__ void gemm_core(const __half* __restrict__ Ah,
                                          const float*  __restrict__ Af,
                                          const __half* __restrict__ Bg,
                                          unsigned* psm, int bm, int bn,
                                          float acc[4][BN / 32][4])
{
    constexpr int NJ    = BN / 64;
    constexpr int BBUF  = BN * PLD;
    constexpr int STG_W = ABUF + BBUF;
    constexpr int BCH   = BN / 32;

    const int tid = threadIdx.x, wid = tid >> 5, lane = tid & 31;
    const int wn = (wid & 3) * (BN / 4);
    const int wm = (wid >> 2) * 64;
    const int sr = tid >> 3, sc = tid & 7;

    auto stageB = [&](int t) {
        unsigned* buf = psm + (t % 3) * STG_W;
        if constexpr (!AF32) {
            #pragma unroll
            for (int i = 0; i < 4; i++) {
                int r = sr + i * 32;
                cp16(smem_u32(buf + r * PLD) + sc * 16,
                     Ah + (size_t)(bm + r) * DMODEL + t * 64 + sc * 8);
            }
        }
        #pragma unroll
        for (int i = 0; i < BCH; i++) {
            int r = sr + i * 32;
            cp16(smem_u32(buf + ABUF + r * PLD) + sc * 16,
                 Bg + (size_t)(bn + r) * DMODEL + t * 64 + sc * 8);
        }
        cp_commit();
    };

    const int ar0 = tid >> 4, ac = tid & 15;
    float4 areg[AF32 ? 8 : 1];
    auto ldgA = [&](int t) {
        if constexpr (AF32) {
            #pragma unroll
            for (int i = 0; i < 8; i++) {
                int r = ar0 + i * 16;
                areg[i] = *reinterpret_cast<const float4*>(
                    Af + (size_t)(bm + r) * DMODEL + t * 64 + ac * 4);
            }
        }
    };
    auto stsA = [&](int t) {
        if constexpr (AF32) {
            unsigned* buf = psm + (t % 3) * STG_W;
            #pragma unroll
            for (int i = 0; i < 8; i++) {
                int r = ar0 + i * 16;
                uint2 u;
                u.x = pack_h2(areg[i].x, areg[i].y);
                u.y = pack_h2(areg[i].z, areg[i].w);
                *reinterpret_cast<uint2*>(
                    reinterpret_cast<char*>(buf + r * PLD) + ac * 8) = u;
            }
        }
    };

    #pragma unroll
    for (int i = 0; i < 4; i++)
        #pragma unroll
        for (int j = 0; j < BN / 32; j++)
            #pragma unroll
            for (int q = 0; q < 4; q++) acc[i][j][q] = 0.f;

    const unsigned aoff = ((wm + (lane & 15)) * PLD + ((lane >> 4) << 2)) * 4;
    const unsigned boff = (ABUF + (wn + (lane & 7) + ((lane >> 4) << 3)) * PLD
                           + (((lane >> 3) & 1) << 2)) * 4;

    if constexpr (AF32) {
        ldgA(0); stsA(0);
        ldgA(1); stsA(1);
    }
    stageB(0); stageB(1);

    for (int t = 0; t < 12; t++) {
        if (t < 11) cp_wait<1>();
        else        cp_wait<0>();
        __syncthreads();
        if (t + 2 < 12) { stageB(t + 2); ldgA(t + 2); }

        unsigned base = smem_u32(psm + (t % 3) * STG_W);
        #pragma unroll
        for (int kk = 0; kk < 4; kk++) {
            unsigned af[4][4], bf[NJ][4];
            #pragma unroll
            for (int i = 0; i < 4; i++)
                ldsm_x4(af[i], base + aoff + i * (16 * PLD * 4) + kk * 32);
            #pragma unroll
            for (int jp = 0; jp < NJ; jp++)
                ldsm_x4(bf[jp], base + boff + jp * (16 * PLD * 4) + kk * 32);
            #pragma unroll
            for (int jp = 0; jp < NJ; jp++)
                #pragma unroll
                for (int i = 0; i < 4; i++) {
                    mma16(acc[i][2 * jp],     af[i], bf[jp]);
                    mma16(acc[i][2 * jp + 1], af[i], bf[jp] + 2);
                }
        }
        if (t + 2 < 12) stsA(t + 2);
    }
}

#define PJ_SMEM_QKV (3 * (ABUF + 256 * PLD) * 4)   // 165888 B
#define PJ_SMEM_O   (3 * (ABUF + 192 * PLD) * 4)   // 138240 B

// ---- fused Q/K/V projection (BN=256, fp32 A): blockIdx.z = problem ---------
__global__ __launch_bounds__(256, 1)
void proj_qkv(const float* __restrict__ xq, const float* __restrict__ xk,
              const float* __restrict__ xv,
              const float* __restrict__ bq, const float* __restrict__ bk,
              const float* __restrict__ bv)
{
    extern __shared__ unsigned psm[];
    const int mode = blockIdx.z;                 // 0=Q 1=K 2=V
    const int bm = blockIdx.y * 128, bn = blockIdx.x * 256;
    const int tid = threadIdx.x, wid = tid >> 5, lane = tid & 31;
    const int rq = lane >> 2, cq = lane & 3;
    const int wm = (wid >> 2) * 64, wn = (wid & 3) * 64;

    const float* Af = (mode == 0) ? xq : (mode == 1) ? xk : xv;
    const __half* Bg = (mode == 0) ? g_wq : (mode == 1) ? g_wk : g_wv;
    const float* bias = (mode == 0) ? bq : (mode == 1) ? bk : bv;
    const float bsc = (mode == 0) ? CEXP : 1.0f;   // bq scaled to match wq

    // PDL: wait for cvt_w; then signal so flash's blocks can pre-launch
    cudaGridDependencySynchronize();
    cudaTriggerProgrammaticLaunchCompletion();

    float acc[4][8][4];
    gemm_core<256, true>(nullptr, Af, Bg, psm, bm, bn, acc);

    #pragma unroll
    for (int i = 0; i < 4; i++) {
        #pragma unroll
        for (int j = 0; j < 8; j++) {
            int r = bm + wm + i * 16 + rq;
            int c = bn + wn + j * 8 + 2 * cq;
            float b0 = bias[c] * bsc, b1 = bias[c + 1] * bsc;
            float v00 = acc[i][j][0] + b0, v01 = acc[i][j][1] + b1;
            float v10 = acc[i][j][2] + b0, v11 = acc[i][j][3] + b1;
            int h = c >> 6, d = c & (DK - 1);
            if (mode == 2) {
                auto put = [&](int row, int dd, float v) {
                    int b = row >> 10, s = row & (S_LEN - 1);
                    g_vt[(((size_t)(b * NH + h)) * DK + dd) * S_LEN + s] = __float2half(v);
                };
                put(r, d, v00);     put(r, d + 1, v01);
                put(r + 8, d, v10); put(r + 8, d + 1, v11);
            } else {
                __half* dst = (mode == 0) ? g_q : g_k;
                auto put2 = [&](int row, float a, float bb) {
                    int b = row >> 10, s = row & (S_LEN - 1);
                    *reinterpret_cast<unsigned*>(
                        dst + (((size_t)(b * NH + h)) * S_LEN + s) * DK + d) = pack_h2(a, bb);
                };
                put2(r, v00, v01);
                put2(r + 8, v10, v11);
            }
        }
    }
}

// ---- output projection (BN=192, fp16 A=g_c) ---------------------------------
// No gridsync: spins on per-row-block counters so it can execute INSIDE
// flash_attn's tail wave (fills idle SMs).
__global__ __launch_bounds__(256, 1)
void proj_o(const float* __restrict__ bias, float* __restrict__ Og)
{
    extern __shared__ unsigned psm[];
    const int ib = blockIdx.y;                   // row-block = b*8 + qt
    const int bm = ib * 128, bn = blockIdx.x * 192;
    const int tid = threadIdx.x, wid = tid >> 5, lane = tid & 31;
    const int rq = lane >> 2, cq = lane & 3;
    const int wm = (wid >> 2) * 64, wn = (wid & 3) * 48;

    // wait for the 12 flash CTAs (all heads) covering this row block
    if (tid == 0) {
        while (atomicAdd(&g_cnt[ib], 0u) < (unsigned)NH) { }
        __threadfence();
    }
    __syncthreads();

    float acc[4][6][4];
    gemm_core<192, false>(g_c, nullptr, g_wo, psm, bm, bn, acc);

    #pragma unroll
    for (int i = 0; i < 4; i++) {
        #pragma unroll
        for (int j = 0; j < 6; j++) {
            int r = bm + wm + i * 16 + rq;
            int c = bn + wn + j * 8 + 2 * cq;
            float b0 = bias[c], b1 = bias[c + 1];
            float2 v0; v0.x = acc[i][j][0] + b0; v0.y = acc[i][j][1] + b1;
            float2 v1; v1.x = acc[i][j][2] + b0; v1.y = acc[i][j][3] + b1;
            *reinterpret_cast<float2*>(Og + (size_t)r * DMODEL + c)       = v0;
            *reinterpret_cast<float2*>(Og + (size_t)(r + 8) * DMODEL + c) = v1;
        }
    }
}

// ---------------------------------------------------------------------------
// FP16 flash attention — R14 shape. Triggers PDL at start (so proj_o launches
// into the tail wave) and signals per-row-block completion counters.
// ---------------------------------------------------------------------------
#define FL_S 36
#define FL_KV (64 * FL_S)
#define FA_SMEM ((128 * FL_S + 6 * FL_KV) * 4)   // 73728 B

__global__ __launch_bounds__(256, 2)
void flash_attn()
{
    extern __shared__ __align__(16) unsigned smx[];
    unsigned* sQ = smx;
    unsigned* sK = sQ + 128 * FL_S;
    unsigned* sV = sK + 3 * FL_KV;

    const int z    = blockIdx.y;
    const int qt   = blockIdx.x;
    const int tid  = threadIdx.x;
    const int warp = tid >> 5;
    const int lane = tid & 31;
    const int rq   = lane >> 2;
    const int cq   = lane & 3;

    const __half* Qg = g_q  + (size_t)z * S_LEN * DK + (size_t)qt * 128 * DK;
    const __half* Kg = g_k  + (size_t)z * S_LEN * DK;
    const __half* Vg = g_vt + (size_t)z * DK * S_LEN;

    const int sr = tid >> 2, sc = tid & 3;
    auto stage = [&](int kt) {
        int buf = kt % 3;
        unsigned kdst = smem_u32(&sK[buf * FL_KV + sr * FL_S]);
        const __half* ksrc = Kg + (size_t)(kt * 64 + sr) * DK;
        cp16(kdst + sc * 16,       ksrc + sc * 8);
        cp16(kdst + (sc + 4) * 16, ksrc + (sc + 4) * 8);
        unsigned vdst = smem_u32(&sV[buf * FL_KV + sr * FL_S]);
        const __half* vsrc = Vg + (size_t)sr * S_LEN + kt * 64;
        cp16(vdst + sc * 16,       vsrc + sc * 8);
        cp16(vdst + (sc + 4) * 16, vsrc + (sc + 4) * 8);
        cp_commit();
    };

    // PDL: wait for proj_qkv, then signal so proj_o can pre-launch
    cudaGridDependencySynchronize();
    cudaTriggerProgrammaticLaunchCompletion();

    stage(0);
    stage(1);

    #pragma unroll
    for (int i = 0; i < 8; i++) {
        int idx = tid + i * 256;
        int r = idx >> 4, c = idx & 15;
        uint2 v = *reinterpret_cast<const uint2*>(Qg + r * DK + c * 4);
        *reinterpret_cast<uint2*>(&sQ[r * FL_S + c * 2]) = v;
    }

    float o[8][4];
    #pragma unroll
    for (int j = 0; j < 8; j++)
        #pragma unroll
        for (int q = 0; q < 4; q++) o[j][q] = 0.f;
    float lacc[4] = {0.f, 0.f, 0.f, 0.f};
    const unsigned ones2[2] = {0x3C003C00u, 0x3C003C00u};

    const int ra = warp * 16 + rq;

    const unsigned qaddr = smem_u32(sQ) +
        ((warp * 16 + (lane & 15)) * FL_S + ((lane >> 4) << 2)) * 4;
    const unsigned kvoff =
        (((lane & 7) + ((lane >> 4) << 3)) * FL_S + (((lane >> 3) & 1) << 2)) * 4;

    for (int kt = 0; kt < S_LEN / 64; kt++) {
        if (kt < S_LEN / 64 - 1) cp_wait<1>();
        else                     cp_wait<0>();
        __syncthreads();
        if (kt + 2 < S_LEN / 64) stage(kt + 2);

        const unsigned kaddr = smem_u32(sK + (kt % 3) * FL_KV) + kvoff;
        const unsigned vaddr = smem_u32(sV + (kt % 3) * FL_KV) + kvoff;

        float s[8][4];
        #pragma unroll
        for (int j = 0; j < 8; j++)
            #pragma unroll
            for (int q = 0; q < 4; q++) s[j][q] = 0.f;

        #pragma unroll
        for (int kk = 0; kk < 4; kk++) {
            unsigned a[4];
            ldsm_x4(a, qaddr + kk * 32);
            #pragma unroll
            for (int jp = 0; jp < 4; jp++) {
                unsigned b4[4];
                ldsm_x4(b4, kaddr + jp * (16 * FL_S * 4) + kk * 32);
                mma16(s[2 * jp],     a, b4);
                mma16(s[2 * jp + 1], a, b4 + 2);
            }
        }

        unsigned pf[8][2];
        #pragma unroll
        for (int j = 0; j < 8; j++) {
            pf[j][0] = ex2h2(s[j][0], s[j][1]);
            pf[j][1] = ex2h2(s[j][2], s[j][3]);
        }

        #pragma unroll
        for (int kk = 0; kk < 4; kk++) {
            unsigned a[4] = { pf[2*kk][0], pf[2*kk][1], pf[2*kk+1][0], pf[2*kk+1][1] };
            #pragma unroll
            for (int jp = 0; jp < 4; jp++) {
                unsigned b4[4];
                ldsm_x4(b4, vaddr + jp * (16 * FL_S * 4) + kk * 32);
                mma16(o[2 * jp],     a, b4);
                mma16(o[2 * jp + 1], a, b4 + 2);
            }
            mma16(lacc, a, ones2);
        }
    }

    {
        float inv0 = 1.f / lacc[0], inv1 = 1.f / lacc[2];
        int b = z / NH, h = z % NH;
        int row = qt * 128 + ra;
        __half* base0 = g_c + ((size_t)b * S_LEN + row) * DMODEL + h * DK;
        __half* base1 = base0 + 8 * DMODEL;
        #pragma unroll
        for (int j = 0; j < 8; j++) {
            int cc = j * 8 + 2 * cq;
            *reinterpret_cast<unsigned*>(base0 + cc) = pack_h2(o[j][0] * inv0, o[j][1] * inv0);
            *reinterpret_cast<unsigned*>(base1 + cc) = pack_h2(o[j][2] * inv1, o[j][3] * inv1);
        }
    }

    // signal row-block completion for proj_o
    __syncthreads();
    if (tid == 0) {
        __threadfence();
        atomicAdd(&g_cnt[(z / NH) * 8 + qt], 1u);
    }
}

// ---------------------------------------------------------------------------
// Launch — PDL chain with early triggers + counter-based fine-grained overlap
// ---------------------------------------------------------------------------
template<typename... Args>
static inline void launch_pdl(void (*kern)(Args...), dim3 grid, dim3 block,
                              size_t smem, Args... args)
{
    cudaLaunchAttribute attr[1];
    attr[0].id = cudaLaunchAttributeProgrammaticStreamSerialization;
    attr[0].val.programmaticStreamSerializationAllowed = 1;
    cudaLaunchConfig_t cfg = {};
    cfg.gridDim = grid;
    cfg.blockDim = block;
    cfg.dynamicSmemBytes = smem;
    cfg.stream = 0;
    cfg.attrs = attr;
    cfg.numAttrs = 1;
    cudaLaunchKernelEx(&cfg, kern, args...);
}

extern "C" void kernel_launch(void* const* d_in, const int* in_sizes, int n_in,
                              void* d_out, int out_size)
{
    const float* key   = (const float*)d_in[0];
    const float* query = (const float*)d_in[1];
    const float* value = (const float*)d_in[2];
    const float* Wk    = (const float*)d_in[3];
    const float* bk    = (const float*)d_in[4];
    const float* Wq    = (const float*)d_in[5];
    const float* bq    = (const float*)d_in[6];
    const float* Wv    = (const float*)d_in[7];
    const float* bv    = (const float*)d_in[8];
    const float* Wo    = (const float*)d_in[9];
    const float* bo    = (const float*)d_in[10];
    float* out = (float*)d_out;

    cudaFuncSetAttribute(proj_qkv, cudaFuncAttributeMaxDynamicSharedMemorySize, PJ_SMEM_QKV);
    cudaFuncSetAttribute(proj_o,   cudaFuncAttributeMaxDynamicSharedMemorySize, PJ_SMEM_O);
    cudaFuncSetAttribute(flash_attn, cudaFuncAttributeMaxDynamicSharedMemorySize, FA_SMEM);

    cvt_w<<<CVT_BLOCKS, 256>>>(Wq, Wk, Wv, Wo);

    launch_pdl(proj_qkv, dim3(DMODEL / 256, MTOT / 128, 3), dim3(256),
               (size_t)PJ_SMEM_QKV, query, key, value, bq, bk, bv);

    launch_pdl(flash_attn, dim3(S_LEN / 128, BATCH * NH), dim3(256),
               (size_t)FA_SMEM);

    launch_pdl(proj_o, dim3(DMODEL / 192, MTOT / 128), dim3(256),
               (size_t)PJ_SMEM_O, bo, out);
}